// round 10
// baseline (speedup 1.0000x reference)
#include <cuda_runtime.h>
#include <cuda_fp16.h>
#include <cstdint>

#define NN 8192
#define PP 49
#define FF 256
#define EE 256
#define HH 256
#define SS 128
#define MTOT (NN * PP)  // 401408

// Scratch (no allocations allowed)
__device__ float  g_x2[NN * EE];      // 8 MB
__device__ __half g_w1h[EE * FF];     // 128 KB, fp16 W1 [e][k]
__device__ float  g_rowsum[NN * FF];  // 8 MB, sum_p x[n,p,f]
__device__ float  g_scores[NN];
__device__ float  g_attn[NN];

// ---------------------------------------------------------------------------
// helpers
// ---------------------------------------------------------------------------
__device__ __forceinline__ uint32_t smem_u32(const void* p) {
    uint32_t a;
    asm("{ .reg .u64 t; cvta.to.shared.u64 t, %1; cvt.u32.u64 %0, t; }" : "=r"(a) : "l"(p));
    return a;
}
__device__ __forceinline__ float ftanh(float x) {   // err ~1e-6 (k1)
    float e = __expf(2.f * x);
    return 1.f - __fdividef(2.f, e + 1.f);
}
__device__ __forceinline__ float tanha(float x) {   // MUFU tanh (epilogue)
    float y;
    asm("tanh.approx.f32 %0, %1;" : "=f"(y) : "f"(x));
    return y;
}

#define LDSM4(r, addr) \
    asm volatile("ldmatrix.sync.aligned.m8n8.x4.shared.b16 {%0,%1,%2,%3}, [%4];" \
        : "=r"((r)[0]), "=r"((r)[1]), "=r"((r)[2]), "=r"((r)[3]) : "r"(addr))

#define MMA16816(c, a, b0v, b1v) \
    asm volatile("mma.sync.aligned.m16n8k16.row.col.f32.f16.f16.f32 " \
        "{%0,%1,%2,%3},{%4,%5,%6,%7},{%8,%9},{%0,%1,%2,%3};" \
        : "+f"((c)[0]), "+f"((c)[1]), "+f"((c)[2]), "+f"((c)[3]) \
        : "r"((a)[0]), "r"((a)[1]), "r"((a)[2]), "r"((a)[3]), "r"(b0v), "r"(b1v))

// named barrier: only the 8 compute warps (256 threads) participate
#define BAR_COMPUTE() asm volatile("bar.sync 1, 256;" ::: "memory")

__device__ __forceinline__ uint32_t pack_h2(float a, float b) {
    __half2 h = __floats2half2_rn(a, b);
    return *(uint32_t*)&h;
}

__global__ void kdummy() {}

// ---------------------------------------------------------------------------
// K1: x2[n,e] = tanh(hidden . W2^T + b2).  fp32 SIMT, 64x64 tiles.
// Also zeroes g_scores + g_rowsum and converts W1 -> fp16.
// ---------------------------------------------------------------------------
__global__ __launch_bounds__(256) void k1_x2(const float* __restrict__ Hm,
                                             const float* __restrict__ W2,
                                             const float* __restrict__ b2,
                                             const float* __restrict__ W1) {
    __shared__ float As[64][17];
    __shared__ float Bs[64][17];
    int tid = threadIdx.x;
    int tx = tid & 15, ty = tid >> 4;
    int nb = blockIdx.y * 64, eb = blockIdx.x * 64;

    int bid = blockIdx.y * gridDim.x + blockIdx.x;  // 0..511
    if (tid < 16) g_scores[bid * 16 + tid] = 0.f;
    if (tid < 128) {
        int i = bid * 128 + tid;
        g_w1h[i] = __float2half_rn(W1[i]);
    }
    // zero rowsum: 2M floats / 512 blocks = 4096 per block = 16/thread
    {
        float4* rs = (float4*)(g_rowsum + (size_t)bid * 4096);
#pragma unroll
        for (int i = 0; i < 4; i++)
            rs[tid + i * 256] = make_float4(0.f, 0.f, 0.f, 0.f);
    }

    float acc[4][4] = {};
    for (int k0 = 0; k0 < HH; k0 += 16) {
        int r = tid >> 2, c4 = tid & 3;
        float4 va = *(const float4*)&Hm[(size_t)(nb + r) * HH + k0 + c4 * 4];
        float4 vb = *(const float4*)&W2[(size_t)(eb + r) * HH + k0 + c4 * 4];
        As[r][c4 * 4 + 0] = va.x; As[r][c4 * 4 + 1] = va.y;
        As[r][c4 * 4 + 2] = va.z; As[r][c4 * 4 + 3] = va.w;
        Bs[r][c4 * 4 + 0] = vb.x; Bs[r][c4 * 4 + 1] = vb.y;
        Bs[r][c4 * 4 + 2] = vb.z; Bs[r][c4 * 4 + 3] = vb.w;
        __syncthreads();
#pragma unroll
        for (int kk = 0; kk < 16; kk++) {
            float ra[4], rb[4];
#pragma unroll
            for (int i = 0; i < 4; i++) ra[i] = As[ty * 4 + i][kk];
#pragma unroll
            for (int j = 0; j < 4; j++) rb[j] = Bs[tx * 4 + j][kk];
#pragma unroll
            for (int i = 0; i < 4; i++)
#pragma unroll
                for (int j = 0; j < 4; j++) acc[i][j] += ra[i] * rb[j];
        }
        __syncthreads();
    }
#pragma unroll
    for (int i = 0; i < 4; i++)
#pragma unroll
        for (int j = 0; j < 4; j++) {
            int n = nb + ty * 4 + i, e = eb + tx * 4 + j;
            g_x2[(size_t)n * EE + e] = ftanh(acc[i][j] + b2[e]);
        }
}

// ---------------------------------------------------------------------------
// K2: warp-specialized.  Threads 0-255 = R4's proven HMMA kernel verbatim
// (named barrier 1 instead of __syncthreads).  Threads 256-319 = 2 rowsum
// warps: re-read this CTA's 128x256 x-slab (L2-hot, k2 uses 10% DRAM) and
// accumulate sum_p x into g_rowsum in fp32 — runs entirely in the HMMA
// shadow, zero work added to compute warps.
// ---------------------------------------------------------------------------
#define OFF_B1  0        // 1024 B
#define OFF_X2  1024     // 4*260*4 = 4160 -> ends 5184
#define OFF_BW  5248     // 256*528 = 135168 -> ends 140416
#define OFF_A   140416   // 2 * 128*80 = 20480 -> ends 160896
#define A_BUF   10240
#define K2_SMEM 160896

__global__ __launch_bounds__(320, 1) void k2_scores(const float* __restrict__ X,
                                                    const float* __restrict__ b1) {
    extern __shared__ __align__(16) char smem[];
    const int tid = threadIdx.x;
    const int row0 = blockIdx.x * 128;
    const int n0 = row0 / PP;

    if (tid >= 256) {
        // ================= rowsum warps (2 warps, 64 lanes) =================
        const int t2 = tid - 256;                    // 0..63 -> col group t2*4
        const float4* Xb = (const float4*)(X + (size_t)row0 * FF) + t2;
        float4 acc = make_float4(0.f, 0.f, 0.f, 0.f);
        int ncur = n0;
        int rend = (n0 + 1) * PP - row0;             // first n boundary (local)
        for (int r = 0; r < 128; r++) {
            if (r == rend) {
                float* dst = g_rowsum + (size_t)ncur * FF + t2 * 4;
                atomicAdd(dst + 0, acc.x);
                atomicAdd(dst + 1, acc.y);
                atomicAdd(dst + 2, acc.z);
                atomicAdd(dst + 3, acc.w);
                acc = make_float4(0.f, 0.f, 0.f, 0.f);
                ncur++;
                rend += PP;
            }
            float4 v = Xb[(size_t)r * (FF / 4)];
            acc.x += v.x; acc.y += v.y; acc.z += v.z; acc.w += v.w;
        }
        float* dst = g_rowsum + (size_t)ncur * FF + t2 * 4;
        atomicAdd(dst + 0, acc.x);
        atomicAdd(dst + 1, acc.y);
        atomicAdd(dst + 2, acc.z);
        atomicAdd(dst + 3, acc.w);
        return;
    }

    // ==================== compute warps (R4 verbatim) =======================
    float* b1s = (float*)(smem + OFF_B1);
    float* x2s = (float*)(smem + OFF_X2);

    const int w = tid >> 5, lane = tid & 31;
    const int tig = lane & 3, g = lane >> 2;
    const int wm = w >> 2, wn = w & 3;          // warp grid 2(m) x 4(n)

    // ---- prefetch A chunk 0 (this thread's 16 consecutive k-floats) ----
    const float* Xp = X + (size_t)(row0 + (tid >> 1)) * FF + (tid & 1) * 16;
    float4 pr0 = *(const float4*)(Xp + 0);
    float4 pr1 = *(const float4*)(Xp + 4);
    float4 pr2 = *(const float4*)(Xp + 8);
    float4 pr3 = *(const float4*)(Xp + 12);

    // ---- B preload: g_w1h (128KB) -> padded smem rows (528B stride) ----
    {
        const uint4* Wp = (const uint4*)g_w1h;
        for (int i = tid; i < 8192; i += 256) {
            int r = i >> 5, s2 = i & 31;
            *(uint4*)(smem + OFF_BW + r * 528 + s2 * 16) = Wp[i];
        }
    }
    // ---- x2 slice (<=4 distinct n) + b1 ----
    for (int i = tid; i < 4 * EE; i += 256) {
        int s = i >> 8, e = i & 255;
        int n = n0 + s;
        x2s[s * 260 + e] = (n < NN) ? g_x2[(size_t)n * EE + e] : 0.f;
    }
    if (tid < EE) b1s[tid] = b1[tid];

    float acc[4][8][4];
#pragma unroll
    for (int mt = 0; mt < 4; mt++)
#pragma unroll
        for (int nt = 0; nt < 8; nt++)
#pragma unroll
            for (int i = 0; i < 4; i++) acc[mt][nt][i] = 0.f;

    const uint32_t sb = smem_u32(smem);
    const int arow = lane & 15, asel = lane >> 4;
    const uint32_t aAddr0 = sb + OFF_A + (uint32_t)(wm * 64 + arow) * 80 + asel * 16;
    const int brow = (lane & 7) + ((lane >> 4) << 3), bsel = (lane >> 3) & 1;
    const uint32_t bAddr0 = sb + OFF_BW + (uint32_t)(wn * 64 + brow) * 528 + bsel * 16;
    char* stsP = smem + OFF_A + (tid >> 1) * 80 + (tid & 1) * 32;

    for (int kc = 0; kc < 8; kc++) {
        const int buf = kc & 1;
        const uint32_t bo = buf * A_BUF;
        // store prefetched A chunk (fp32 -> fp16)
        {
            uint4 q0, q1;
            q0.x = pack_h2(pr0.x, pr0.y); q0.y = pack_h2(pr0.z, pr0.w);
            q0.z = pack_h2(pr1.x, pr1.y); q0.w = pack_h2(pr1.z, pr1.w);
            q1.x = pack_h2(pr2.x, pr2.y); q1.y = pack_h2(pr2.z, pr2.w);
            q1.z = pack_h2(pr3.x, pr3.y); q1.w = pack_h2(pr3.z, pr3.w);
            *(uint4*)(stsP + bo) = q0;
            *(uint4*)(stsP + bo + 16) = q1;
        }
        BAR_COMPUTE();
        // prefetch next chunk
        if (kc < 7) {
            const float* Xn = Xp + (kc + 1) * 32;
            pr0 = *(const float4*)(Xn + 0);
            pr1 = *(const float4*)(Xn + 4);
            pr2 = *(const float4*)(Xn + 8);
            pr3 = *(const float4*)(Xn + 12);
        }
        // compute: 2 x k16 steps
#pragma unroll
        for (int ks = 0; ks < 2; ks++) {
            uint32_t Ar[4][4], Br[4][4];
#pragma unroll
            for (int mt = 0; mt < 4; mt++)
                LDSM4(Ar[mt], aAddr0 + bo + mt * (16 * 80) + ks * 32);
#pragma unroll
            for (int np = 0; np < 4; np++)
                LDSM4(Br[np], bAddr0 + np * (16 * 528) + kc * 64 + ks * 32);
#pragma unroll
            for (int mt = 0; mt < 4; mt++)
#pragma unroll
                for (int nt = 0; nt < 8; nt++)
                    MMA16816(acc[mt][nt], Ar[mt], Br[nt >> 1][(nt & 1) * 2],
                             Br[nt >> 1][(nt & 1) * 2 + 1]);
        }
        // per-warp order STS(buf) -> bar -> reads(buf): 1 bar/iter is safe
    }

    // ---- epilogue: tanh.approx + dot(x2) + quad shuffle + atomicAdd ----
    const float inv = 1.f / (float)PP;
    float b0r[8], b1r[8];
#pragma unroll
    for (int nt = 0; nt < 8; nt++) {
        b0r[nt] = b1s[wn * 64 + nt * 8 + tig * 2];
        b1r[nt] = b1s[wn * 64 + nt * 8 + tig * 2 + 1];
    }
#pragma unroll
    for (int mt = 0; mt < 4; mt++) {
        int rA = wm * 64 + mt * 16 + g;
        int rB = rA + 8;
        int nA = (row0 + rA) / PP;
        int nB = (row0 + rB) / PP;
        const float* xA = x2s + (nA - n0) * 260 + wn * 64;
        const float* xB = x2s + (nB - n0) * 260 + wn * 64;
        float sA = 0.f, sB = 0.f;
#pragma unroll
        for (int nt = 0; nt < 8; nt++) {
            int c0 = nt * 8 + tig * 2, c1 = c0 + 1;
            sA += tanha(acc[mt][nt][0] + b0r[nt]) * xA[c0]
                + tanha(acc[mt][nt][1] + b1r[nt]) * xA[c1];
            sB += tanha(acc[mt][nt][2] + b0r[nt]) * xB[c0]
                + tanha(acc[mt][nt][3] + b1r[nt]) * xB[c1];
        }
        sA += __shfl_xor_sync(0xffffffffu, sA, 1);
        sA += __shfl_xor_sync(0xffffffffu, sA, 2);
        sB += __shfl_xor_sync(0xffffffffu, sB, 1);
        sB += __shfl_xor_sync(0xffffffffu, sB, 2);
        if (tig == 0) {
            atomicAdd(&g_scores[nA], sA * inv);
            atomicAdd(&g_scores[nB], sB * inv);
        }
    }
}

// ---------------------------------------------------------------------------
// K3: per-segment softmax over scalar scores (patch_lens int32 or int64).
// ---------------------------------------------------------------------------
__device__ __forceinline__ int seg_len(const int* p32, int is64, int i) {
    return is64 ? p32[2 * i] : p32[i];
}

__global__ __launch_bounds__(128) void k3_softmax(const int* __restrict__ lens32) {
    __shared__ float sh[128];
    __shared__ int s_off, s_len;
    int s = blockIdx.x, tid = threadIdx.x;
    if (tid == 0) {
        int is64 = (lens32[1] == 0) ? 1 : 0;
        int o = 0;
        for (int i = 0; i < s; i++) o += seg_len(lens32, is64, i);
        s_off = o;
        s_len = seg_len(lens32, is64, s);
    }
    __syncthreads();
    int off = s_off, len = s_len;
    float v = (tid < len) ? g_scores[off + tid] : -1e30f;
    sh[tid] = v;
    __syncthreads();
    for (int st = 64; st > 0; st >>= 1) {
        if (tid < st) sh[tid] = fmaxf(sh[tid], sh[tid + st]);
        __syncthreads();
    }
    float m = sh[0];
    __syncthreads();
    float e = (tid < len) ? expf(v - m) : 0.f;
    sh[tid] = e;
    __syncthreads();
    for (int st = 64; st > 0; st >>= 1) {
        if (tid < st) sh[tid] += sh[tid + st];
        __syncthreads();
    }
    float z = sh[0];
    if (tid < len) g_attn[off + tid] = e / z;
}

// ---------------------------------------------------------------------------
// K4b: out[n,f] = attn[n] * g_rowsum[n][f]   (tiny: 16 MB traffic, ~5us)
// ---------------------------------------------------------------------------
__global__ __launch_bounds__(256) void k4_out(float* __restrict__ out) {
    int idx = blockIdx.x * 256 + threadIdx.x;   // float4 index, 524288 total
    int n = idx >> 6;                            // 64 float4 per row
    float a = g_attn[n];
    float4 v = ((const float4*)g_rowsum)[idx];
    v.x *= a; v.y *= a; v.z *= a; v.w *= a;
    ((float4*)out)[idx] = v;
}

// ---------------------------------------------------------------------------
extern "C" void kernel_launch(void* const* d_in, const int* in_sizes, int n_in,
                              void* d_out, int out_size) {
    const float* x      = (const float*)d_in[0];  // [8192,49,256]
    const float* hidden = (const float*)d_in[1];  // [1,8192,256]
    const float* W1     = (const float*)d_in[2];  // [256,256]
    const float* b1     = (const float*)d_in[3];  // [256]
    const float* W2     = (const float*)d_in[4];  // [256,256]
    const float* b2     = (const float*)d_in[5];  // [256]
    const int* pl       = (const int*)d_in[6];    // [128] int32 or int64

    float* out = (float*)d_out;

    static int attr_set = 0;
    if (!attr_set) {
        cudaFuncSetAttribute(k2_scores, cudaFuncAttributeMaxDynamicSharedMemorySize, K2_SMEM);
        attr_set = 1;
    }

    // 6-launch pattern with k2 at slot 4 — same capture position as R8/R9
    kdummy<<<1, 32>>>();
    kdummy<<<1, 32>>>();
    k1_x2<<<dim3(4, 128), 256>>>(hidden, W2, b2, W1);
    k2_scores<<<MTOT / 128, 320, K2_SMEM>>>(x, b1);
    k3_softmax<<<SS, 128>>>(pl);
    k4_out<<<2048, 256>>>(out);
}

// round 11
// speedup vs baseline: 1.1800x; 1.1800x over previous
#include <cuda_runtime.h>
#include <cuda_fp16.h>
#include <cstdint>

#define NN 8192
#define PP 49
#define FF 256
#define EE 256
#define HH 256
#define SS 128
#define MTOT (NN * PP)  // 401408

// Scratch (no allocations allowed)
__device__ float  g_x2[NN * EE];      // 8 MB
__device__ __half g_w1h[EE * FF];     // 128 KB, fp16 W1 [e][k]
__device__ float  g_rowsum[NN * FF];  // 8 MB, sum_p x[n,p,f]
__device__ float  g_scores[NN];
__device__ float  g_attn[NN];

// ---------------------------------------------------------------------------
// helpers
// ---------------------------------------------------------------------------
__device__ __forceinline__ uint32_t smem_u32(const void* p) {
    uint32_t a;
    asm("{ .reg .u64 t; cvta.to.shared.u64 t, %1; cvt.u32.u64 %0, t; }" : "=r"(a) : "l"(p));
    return a;
}
__device__ __forceinline__ float ftanh(float x) {   // err ~1e-6 (k1)
    float e = __expf(2.f * x);
    return 1.f - __fdividef(2.f, e + 1.f);
}
__device__ __forceinline__ float tanha(float x) {   // MUFU tanh (epilogue)
    float y;
    asm("tanh.approx.f32 %0, %1;" : "=f"(y) : "f"(x));
    return y;
}

#define LDSM4(r, addr) \
    asm volatile("ldmatrix.sync.aligned.m8n8.x4.shared.b16 {%0,%1,%2,%3}, [%4];" \
        : "=r"((r)[0]), "=r"((r)[1]), "=r"((r)[2]), "=r"((r)[3]) : "r"(addr))

#define MMA16816(c, a, b0v, b1v) \
    asm volatile("mma.sync.aligned.m16n8k16.row.col.f32.f16.f16.f32 " \
        "{%0,%1,%2,%3},{%4,%5,%6,%7},{%8,%9},{%0,%1,%2,%3};" \
        : "+f"((c)[0]), "+f"((c)[1]), "+f"((c)[2]), "+f"((c)[3]) \
        : "r"((a)[0]), "r"((a)[1]), "r"((a)[2]), "r"((a)[3]), "r"(b0v), "r"(b1v))

__device__ __forceinline__ uint32_t pack_h2(float a, float b) {
    __half2 h = __floats2half2_rn(a, b);
    return *(uint32_t*)&h;
}

__global__ void kdummy() {}

// ---------------------------------------------------------------------------
// K1: x2[n,e] = tanh(hidden . W2^T + b2).  fp32 SIMT, 64x64 tiles.
// Also zeroes g_scores and converts W1 -> fp16.
// ---------------------------------------------------------------------------
__global__ __launch_bounds__(256) void k1_x2(const float* __restrict__ Hm,
                                             const float* __restrict__ W2,
                                             const float* __restrict__ b2,
                                             const float* __restrict__ W1) {
    __shared__ float As[64][17];
    __shared__ float Bs[64][17];
    int tid = threadIdx.x;
    int tx = tid & 15, ty = tid >> 4;
    int nb = blockIdx.y * 64, eb = blockIdx.x * 64;

    int bid = blockIdx.y * gridDim.x + blockIdx.x;  // 0..511
    if (tid < 16) g_scores[bid * 16 + tid] = 0.f;
    if (tid < 128) {
        int i = bid * 128 + tid;
        g_w1h[i] = __float2half_rn(W1[i]);
    }

    float acc[4][4] = {};
    for (int k0 = 0; k0 < HH; k0 += 16) {
        int r = tid >> 2, c4 = tid & 3;
        float4 va = *(const float4*)&Hm[(size_t)(nb + r) * HH + k0 + c4 * 4];
        float4 vb = *(const float4*)&W2[(size_t)(eb + r) * HH + k0 + c4 * 4];
        As[r][c4 * 4 + 0] = va.x; As[r][c4 * 4 + 1] = va.y;
        As[r][c4 * 4 + 2] = va.z; As[r][c4 * 4 + 3] = va.w;
        Bs[r][c4 * 4 + 0] = vb.x; Bs[r][c4 * 4 + 1] = vb.y;
        Bs[r][c4 * 4 + 2] = vb.z; Bs[r][c4 * 4 + 3] = vb.w;
        __syncthreads();
#pragma unroll
        for (int kk = 0; kk < 16; kk++) {
            float ra[4], rb[4];
#pragma unroll
            for (int i = 0; i < 4; i++) ra[i] = As[ty * 4 + i][kk];
#pragma unroll
            for (int j = 0; j < 4; j++) rb[j] = Bs[tx * 4 + j][kk];
#pragma unroll
            for (int i = 0; i < 4; i++)
#pragma unroll
                for (int j = 0; j < 4; j++) acc[i][j] += ra[i] * rb[j];
        }
        __syncthreads();
    }
#pragma unroll
    for (int i = 0; i < 4; i++)
#pragma unroll
        for (int j = 0; j < 4; j++) {
            int n = nb + ty * 4 + i, e = eb + tx * 4 + j;
            g_x2[(size_t)n * EE + e] = ftanh(acc[i][j] + b2[e]);
        }
}

// ---------------------------------------------------------------------------
// K2: R4 verbatim — best measured config (466us).  fp16 mma m16n8k16, f32
// acc, CTA = 128 rows x 256 e, W1 resident in SMEM, reg-prefetch LDG ->
// pack f16 -> STS, double-buffered, 1 sync per k-chunk.
// ---------------------------------------------------------------------------
#define OFF_B1  0        // 1024 B
#define OFF_X2  1024     // 4*260*4 = 4160 -> ends 5184
#define OFF_BW  5248     // 256*528 = 135168 -> ends 140416
#define OFF_A   140416   // 2 * 128*80 = 20480 -> ends 160896
#define A_BUF   10240
#define K2_SMEM 160896

__global__ __launch_bounds__(256, 1) void k2_scores(const float* __restrict__ X,
                                                    const float* __restrict__ b1) {
    extern __shared__ __align__(16) char smem[];
    float* b1s = (float*)(smem + OFF_B1);
    float* x2s = (float*)(smem + OFF_X2);

    const int tid = threadIdx.x;
    const int w = tid >> 5, lane = tid & 31;
    const int tig = lane & 3, g = lane >> 2;
    const int wm = w >> 2, wn = w & 3;          // warp grid 2(m) x 4(n)
    const int row0 = blockIdx.x * 128;
    const int n0 = row0 / PP;

    // ---- prefetch A chunk 0 (this thread's 16 consecutive k-floats) ----
    const float* Xp = X + (size_t)(row0 + (tid >> 1)) * FF + (tid & 1) * 16;
    float4 pr0 = *(const float4*)(Xp + 0);
    float4 pr1 = *(const float4*)(Xp + 4);
    float4 pr2 = *(const float4*)(Xp + 8);
    float4 pr3 = *(const float4*)(Xp + 12);

    // ---- B preload: g_w1h (128KB) -> padded smem rows (528B stride) ----
    {
        const uint4* Wp = (const uint4*)g_w1h;
        for (int i = tid; i < 8192; i += 256) {
            int r = i >> 5, s2 = i & 31;
            *(uint4*)(smem + OFF_BW + r * 528 + s2 * 16) = Wp[i];
        }
    }
    // ---- x2 slice (<=4 distinct n) + b1 ----
    for (int i = tid; i < 4 * EE; i += 256) {
        int s = i >> 8, e = i & 255;
        int n = n0 + s;
        x2s[s * 260 + e] = (n < NN) ? g_x2[(size_t)n * EE + e] : 0.f;
    }
    if (tid < EE) b1s[tid] = b1[tid];

    float acc[4][8][4];
#pragma unroll
    for (int mt = 0; mt < 4; mt++)
#pragma unroll
        for (int nt = 0; nt < 8; nt++)
#pragma unroll
            for (int i = 0; i < 4; i++) acc[mt][nt][i] = 0.f;

    const uint32_t sb = smem_u32(smem);
    const int arow = lane & 15, asel = lane >> 4;
    const uint32_t aAddr0 = sb + OFF_A + (uint32_t)(wm * 64 + arow) * 80 + asel * 16;
    const int brow = (lane & 7) + ((lane >> 4) << 3), bsel = (lane >> 3) & 1;
    const uint32_t bAddr0 = sb + OFF_BW + (uint32_t)(wn * 64 + brow) * 528 + bsel * 16;
    char* stsP = smem + OFF_A + (tid >> 1) * 80 + (tid & 1) * 32;

    for (int kc = 0; kc < 8; kc++) {
        const int buf = kc & 1;
        const uint32_t bo = buf * A_BUF;
        // store prefetched A chunk (fp32 -> fp16)
        {
            uint4 q0, q1;
            q0.x = pack_h2(pr0.x, pr0.y); q0.y = pack_h2(pr0.z, pr0.w);
            q0.z = pack_h2(pr1.x, pr1.y); q0.w = pack_h2(pr1.z, pr1.w);
            q1.x = pack_h2(pr2.x, pr2.y); q1.y = pack_h2(pr2.z, pr2.w);
            q1.z = pack_h2(pr3.x, pr3.y); q1.w = pack_h2(pr3.z, pr3.w);
            *(uint4*)(stsP + bo) = q0;
            *(uint4*)(stsP + bo + 16) = q1;
        }
        __syncthreads();
        // prefetch next chunk
        if (kc < 7) {
            const float* Xn = Xp + (kc + 1) * 32;
            pr0 = *(const float4*)(Xn + 0);
            pr1 = *(const float4*)(Xn + 4);
            pr2 = *(const float4*)(Xn + 8);
            pr3 = *(const float4*)(Xn + 12);
        }
        // compute: 2 x k16 steps
#pragma unroll
        for (int ks = 0; ks < 2; ks++) {
            uint32_t Ar[4][4], Br[4][4];
#pragma unroll
            for (int mt = 0; mt < 4; mt++)
                LDSM4(Ar[mt], aAddr0 + bo + mt * (16 * 80) + ks * 32);
#pragma unroll
            for (int np = 0; np < 4; np++)
                LDSM4(Br[np], bAddr0 + np * (16 * 528) + kc * 64 + ks * 32);
#pragma unroll
            for (int mt = 0; mt < 4; mt++)
#pragma unroll
                for (int nt = 0; nt < 8; nt++)
                    MMA16816(acc[mt][nt], Ar[mt], Br[nt >> 1][(nt & 1) * 2],
                             Br[nt >> 1][(nt & 1) * 2 + 1]);
        }
        // per-warp order STS(buf) -> sync -> reads(buf): 1 sync/iter is safe
    }

    // ---- epilogue: tanh.approx + dot(x2) + quad shuffle + atomicAdd ----
    const float inv = 1.f / (float)PP;
    float b0r[8], b1r[8];
#pragma unroll
    for (int nt = 0; nt < 8; nt++) {
        b0r[nt] = b1s[wn * 64 + nt * 8 + tig * 2];
        b1r[nt] = b1s[wn * 64 + nt * 8 + tig * 2 + 1];
    }
#pragma unroll
    for (int mt = 0; mt < 4; mt++) {
        int rA = wm * 64 + mt * 16 + g;
        int rB = rA + 8;
        int nA = (row0 + rA) / PP;
        int nB = (row0 + rB) / PP;
        const float* xA = x2s + (nA - n0) * 260 + wn * 64;
        const float* xB = x2s + (nB - n0) * 260 + wn * 64;
        float sA = 0.f, sB = 0.f;
#pragma unroll
        for (int nt = 0; nt < 8; nt++) {
            int c0 = nt * 8 + tig * 2, c1 = c0 + 1;
            sA += tanha(acc[mt][nt][0] + b0r[nt]) * xA[c0]
                + tanha(acc[mt][nt][1] + b1r[nt]) * xA[c1];
            sB += tanha(acc[mt][nt][2] + b0r[nt]) * xB[c0]
                + tanha(acc[mt][nt][3] + b1r[nt]) * xB[c1];
        }
        sA += __shfl_xor_sync(0xffffffffu, sA, 1);
        sA += __shfl_xor_sync(0xffffffffu, sA, 2);
        sB += __shfl_xor_sync(0xffffffffu, sB, 1);
        sB += __shfl_xor_sync(0xffffffffu, sB, 2);
        if (tig == 0) {
            atomicAdd(&g_scores[nA], sA * inv);
            atomicAdd(&g_scores[nB], sB * inv);
        }
    }
}

// ---------------------------------------------------------------------------
// K4a: rowsum[n][f] = sum_p x[n,p,f].  Runs on a SIDE STREAM concurrently
// with k2 (k2 uses ~10% DRAM; this is pure DRAM ~55us -> hidden).
// Direct store, no atomics, no zero-init needed.
// ---------------------------------------------------------------------------
__global__ __launch_bounds__(256) void k4a_rowsum(const float* __restrict__ X) {
    int n = blockIdx.x, f = threadIdx.x;
    const float* xp = X + (size_t)n * PP * FF + f;
    float acc = 0.f;
#pragma unroll
    for (int p = 0; p < PP; p++) acc += xp[(size_t)p * FF];
    g_rowsum[(size_t)n * FF + f] = acc;
}

// ---------------------------------------------------------------------------
// K3: per-segment softmax over scalar scores (patch_lens int32 or int64).
// ---------------------------------------------------------------------------
__device__ __forceinline__ int seg_len(const int* p32, int is64, int i) {
    return is64 ? p32[2 * i] : p32[i];
}

__global__ __launch_bounds__(128) void k3_softmax(const int* __restrict__ lens32) {
    __shared__ float sh[128];
    __shared__ int s_off, s_len;
    int s = blockIdx.x, tid = threadIdx.x;
    if (tid == 0) {
        int is64 = (lens32[1] == 0) ? 1 : 0;
        int o = 0;
        for (int i = 0; i < s; i++) o += seg_len(lens32, is64, i);
        s_off = o;
        s_len = seg_len(lens32, is64, s);
    }
    __syncthreads();
    int off = s_off, len = s_len;
    float v = (tid < len) ? g_scores[off + tid] : -1e30f;
    sh[tid] = v;
    __syncthreads();
    for (int st = 64; st > 0; st >>= 1) {
        if (tid < st) sh[tid] = fmaxf(sh[tid], sh[tid + st]);
        __syncthreads();
    }
    float m = sh[0];
    __syncthreads();
    float e = (tid < len) ? expf(v - m) : 0.f;
    sh[tid] = e;
    __syncthreads();
    for (int st = 64; st > 0; st >>= 1) {
        if (tid < st) sh[tid] += sh[tid + st];
        __syncthreads();
    }
    float z = sh[0];
    if (tid < len) g_attn[off + tid] = e / z;
}

// ---------------------------------------------------------------------------
// K4b: out[n,f] = attn[n] * g_rowsum[n][f]   (tiny: 16 MB traffic, ~5us)
// ---------------------------------------------------------------------------
__global__ __launch_bounds__(256) void k4_out(float* __restrict__ out) {
    int idx = blockIdx.x * 256 + threadIdx.x;   // float4 index, 524288 total
    int n = idx >> 6;                            // 64 float4 per row
    float a = g_attn[n];
    float4 v = ((const float4*)g_rowsum)[idx];
    v.x *= a; v.y *= a; v.z *= a; v.w *= a;
    ((float4*)out)[idx] = v;
}

// ---------------------------------------------------------------------------
extern "C" void kernel_launch(void* const* d_in, const int* in_sizes, int n_in,
                              void* d_out, int out_size) {
    const float* x      = (const float*)d_in[0];  // [8192,49,256]
    const float* hidden = (const float*)d_in[1];  // [1,8192,256]
    const float* W1     = (const float*)d_in[2];  // [256,256]
    const float* b1     = (const float*)d_in[3];  // [256]
    const float* W2     = (const float*)d_in[4];  // [256,256]
    const float* b2     = (const float*)d_in[5];  // [256]
    const int* pl       = (const int*)d_in[6];    // [128] int32 or int64

    float* out = (float*)d_out;

    static bool s_init = false;
    static cudaStream_t s_side;
    static cudaEvent_t s_eFork, s_eJoin;
    if (!s_init) {
        cudaFuncSetAttribute(k2_scores, cudaFuncAttributeMaxDynamicSharedMemorySize, K2_SMEM);
        cudaStreamCreateWithFlags(&s_side, cudaStreamNonBlocking);
        cudaEventCreateWithFlags(&s_eFork, cudaEventDisableTiming);
        cudaEventCreateWithFlags(&s_eJoin, cudaEventDisableTiming);
        s_init = true;
    }

    // main stream: dummies (ncu slot), k1, then k2
    kdummy<<<1, 32>>>();
    kdummy<<<1, 32>>>();
    k1_x2<<<dim3(4, 128), 256>>>(hidden, W2, b2, W1);

    // fork: side stream runs the DRAM-bound rowsum concurrently with k2
    cudaEventRecord(s_eFork, 0);
    cudaStreamWaitEvent(s_side, s_eFork, 0);

    k2_scores<<<MTOT / 128, 256, K2_SMEM>>>(x, b1);
    k4a_rowsum<<<NN, 256, 0, s_side>>>(x);

    // join: k3/k4b need both scores (k2) and rowsum (k4a)
    cudaEventRecord(s_eJoin, s_side);
    cudaStreamWaitEvent(0, s_eJoin, 0);

    k3_softmax<<<SS, 128>>>(pl);
    k4_out<<<2048, 256>>>(out);
}